// round 15
// baseline (speedup 1.0000x reference)
#include <cuda_runtime.h>

// ---------------------------------------------------------------------------
// Caps2dMatwo fused kernel, v10 = v7b (49.6us) + LDS.128 conv taps.
// Shapes: N=2, T0=4 (c), T1=8, H=W=128, PD=AD=4, Z=32, KS=3, ROUTINGS=3.
//
// v10 vs v7b:
//  - x tile z-stride 34 -> 36 (16B-aligned z-quads): each conv tap is one
//    LDS.128 (36 tap loads/thread instead of 72), conflict-free.
//  - phase C / routing / exchange: IDENTICAL to v7b (s warp-uniform,
//    barrier + smem exchange with tid^128; shuffle variants regressed).
// ---------------------------------------------------------------------------

typedef unsigned long long ull;

#define SX_SIZE   (4*3*18*36)          // 7776 floats: [(c*3+kh)*18+col]*36+z
#define CV_PSTR   36
#define CV_SIZE   (32*16*CV_PSTR)      // 18432 floats: [(c*8+ch)*16+pix]*36+z
#define SMEM_FLOATS (SX_SIZE + CV_SIZE + 288 + 512 + 512 + 128)
#define SMEM_BYTES (SMEM_FLOATS * 4)   // 110,592 bytes -> 2 blocks/SM

__device__ __forceinline__ float sigf(float v) {
    return 1.0f / (1.0f + __expf(-v));
}
__device__ __forceinline__ ull pk(float a, float b) {
    ull r; asm("mov.b64 %0, {%1, %2};" : "=l"(r) : "f"(a), "f"(b)); return r;
}
__device__ __forceinline__ float2 upk(ull v) {
    float2 r; asm("mov.b64 {%0, %1}, %2;" : "=f"(r.x), "=f"(r.y) : "l"(v)); return r;
}
__device__ __forceinline__ ull ffma2(ull a, ull b, ull c) {
    ull d; asm("fma.rn.f32x2 %0, %1, %2, %3;" : "=l"(d) : "l"(a), "l"(b), "l"(c)); return d;
}
__device__ __forceinline__ ull fmul2(ull a, ull b) {
    ull d; asm("mul.rn.f32x2 %0, %1, %2;" : "=l"(d) : "l"(a), "l"(b)); return d;
}

__global__ void __launch_bounds__(256, 2)
caps_kernel(const float* __restrict__ x,     // (2,4,32,128,128)
            const float* __restrict__ Wc,    // (4,3,3,1,8)  flat 288
            const float* __restrict__ Wp,    // (4,16,8)     flat 512
            const float* __restrict__ Wa,    // (4,16,8)     flat 512
            const float* __restrict__ ba,    // (4,8)        flat 32
            float* __restrict__ out)         // (2,8,32,128,128)
{
    extern __shared__ float sm[];
    float* s_x  = sm;                    // 7776, z-innermost; reused as s_ex
    float* s_cv = s_x + SX_SIZE;         // 18432
    float* s_wc = s_cv + CV_SIZE;        // 288  [c][kh*3+kw][t1]
    float* s_mp = s_wc + 288;            // 512  [c][t][j][k] normalized
    float* s_ma = s_mp + 512;            // 512  [c][t][j][k]
    float* s_bb = s_ma + 512;            // 128  [c][t][k] = b_app*sum_j mapp
    float* s_ex = s_x;                   // aliased: phase C only

    const int tid = threadIdx.x;
    const int w0  = blockIdx.x * 16;
    const int h   = blockIdx.y;
    const int n   = blockIdx.z;

    // ---- weights into smem (256-thread safe) ----
    if (tid < 144) {                             // 288 conv weights, 2 each
        s_wc[tid]       = Wc[tid];
        s_wc[tid + 144] = Wc[tid + 144];
    }
    s_ma[tid]       = Wa[tid];
    s_ma[tid + 256] = Wa[tid + 256];
    if (tid < 128) {
        int q = tid;                             // one (c,t,k) each
        int c = q >> 5, t = (q >> 2) & 7, k = q & 3;
        const float* wpp = Wp + c*128 + t*16 + k;
        float m0 = wpp[0], m1 = wpp[4], m2 = wpp[8], m3 = wpp[12];
        float inv = rsqrtf(fmaxf(m0*m0 + m1*m1 + m2*m2 + m3*m3, 1e-12f));
        float* d = s_mp + (c*8 + t)*16 + k;
        d[0] = m0*inv; d[4] = m1*inv; d[8] = m2*inv; d[12] = m3*inv;
        const float* wap = Wa + c*128 + t*16 + k;
        s_bb[(c*8 + t)*4 + k] = ba[c*8 + t] * (wap[0] + wap[4] + wap[8] + wap[12]);
    }

    // ---- x tile loader (z innermost, stride 36).  col 1..16 = w0..w0+15,
    //      col 0 = w0-1, col 17 = w0+16;  rows kh = h-1..h+1.  ----
#pragma unroll
    for (int r3 = 0; r3 < 3; ++r3) {
        const int gr = h + r3 - 1;
        const bool ok = (gr >= 0) && (gr < 128);
#pragma unroll
        for (int it = 0; it < 2; ++it) {
            int unit = tid + it*256;              // cz*4 + colgrp
            int cz   = unit >> 2;
            int col4 = (unit & 3) * 4;
            float4 v = make_float4(0.f, 0.f, 0.f, 0.f);
            if (ok)
                v = *(const float4*)(x + (((long)n*128 + cz)*128 + gr)*128 + w0 + col4);
            int c = cz >> 5, z = cz & 31;
            float* base = s_x + ((c*3 + r3)*18 + 1 + col4)*36 + z;
            base[0]    = v.x;
            base[36]   = v.y;
            base[72]   = v.z;
            base[108]  = v.w;
        }
    }
    {                                             // halo columns
        int cz   = tid & 127;
        int side = tid >> 7;                      // 0 = left, 1 = right
        int c = cz >> 5, z = cz & 31;
        const bool okc = side ? (w0 + 16 < 128) : (w0 > 0);
        const int  gc  = side ? (w0 + 16) : (w0 - 1);
        const int  sc  = side ? 17 : 0;
#pragma unroll
        for (int r3 = 0; r3 < 3; ++r3) {
            int gr = h + r3 - 1;
            float v = 0.f;
            if (okc && gr >= 0 && gr < 128)
                v = x[(((long)n*128 + cz)*128 + gr)*128 + gc];
            s_x[((c*3 + r3)*18 + sc)*36 + z] = v;
        }
    }
    __syncthreads();

    // ---- Phase B: conv, LDS.128 z-quad taps + f32x2.  thread=(c,chh,zh,pix)
    {
        const int c   = tid >> 6;                 // warp-uniform
        const int chh = (tid >> 5) & 1;           // warp-uniform
        const int zh  = (tid >> 4) & 1;           // half-warp
        const int pix = tid & 15;

        ull w2[9][4];                             // (w,w) broadcast pairs
#pragma unroll
        for (int p = 0; p < 9; ++p)
#pragma unroll
            for (int l = 0; l < 4; ++l) {
                float wv = s_wc[(c*9 + p)*8 + chh*4 + l];
                w2[p][l] = pk(wv, wv);
            }

#pragma unroll
        for (int ck = 0; ck < 4; ++ck) {
            const int z0 = zh*16 + ck*4;
            ull acc[4][2];
#pragma unroll
            for (int l = 0; l < 4; ++l) { acc[l][0] = 0ULL; acc[l][1] = 0ULL; }
#pragma unroll
            for (int kh = 0; kh < 3; ++kh)
#pragma unroll
                for (int kw = 0; kw < 3; ++kw) {
                    ulonglong2 xv = *(const ulonglong2*)
                        (s_x + ((c*3 + kh)*18 + pix + kw)*36 + z0);
#pragma unroll
                    for (int l = 0; l < 4; ++l) {
                        acc[l][0] = ffma2(xv.x, w2[kh*3+kw][l], acc[l][0]);
                        acc[l][1] = ffma2(xv.y, w2[kh*3+kw][l], acc[l][1]);
                    }
                }
#pragma unroll
            for (int l = 0; l < 4; ++l)
                *(ulonglong2*)(s_cv + ((c*8 + chh*4 + l)*16 + pix)*CV_PSTR + z0) =
                    make_ulonglong2(acc[l][0], acc[l][1]);
        }
    }
    __syncthreads();

    // ---- Phase C (v7b, verbatim): u_hat f32x2 + routing, barrier exchange.
    //      thread = s*128 + t*16 + pix ----
    {
        const int s   = tid >> 7;                 // warp-uniform
        const int t   = (tid >> 4) & 7;           // half-warp
        const int pix = tid & 15;
        const int t1  = (t >> 1) + (s ? 4 : 0);   // conv channel
        const int zb  = (t & 1) << 4;

        ull u2[4][8];                             // u_hat, z-pairs

        const ull coordp = pk((float)(w0 + pix) * (1.0f/128.0f),
                              (float)h * (1.0f/128.0f));

#pragma unroll
        for (int c = 0; c < 4; ++c) {
            const float* cb = s_cv + ((c*8 + t1)*16 + pix)*CV_PSTR + zb;
            ulonglong2 A  = *(const ulonglong2*)(cb + 0);
            ulonglong2 B  = *(const ulonglong2*)(cb + 4);
            ulonglong2 C2 = *(const ulonglong2*)(cb + 8);
            ulonglong2 D  = *(const ulonglong2*)(cb + 12);
            ull cpr[8] = {A.x, A.y, B.x, B.y, C2.x, C2.y, D.x, D.y};
            ull cb2[16];
#pragma unroll
            for (int m = 0; m < 8; ++m) {
                float2 f = upk(cpr[m]);
                cb2[2*m]   = pk(f.x, f.x);
                cb2[2*m+1] = pk(f.y, f.y);
            }
            if (s == 0) {
                const float* mp = s_mp + (c*8 + t)*16;
#pragma unroll
                for (int i = 0; i < 4; ++i)
#pragma unroll
                    for (int kp = 0; kp < 2; ++kp) {
                        ull a = fmul2(cb2[4*i+0], *(const ull*)(mp + 0  + 2*kp));
                        a = ffma2(cb2[4*i+1], *(const ull*)(mp + 4  + 2*kp), a);
                        a = ffma2(cb2[4*i+2], *(const ull*)(mp + 8  + 2*kp), a);
                        a = ffma2(cb2[4*i+3], *(const ull*)(mp + 12 + 2*kp), a);
                        if (kp == 0) a = ffma2(cb2[4*i+3], coordp, a);
                        u2[c][2*i + kp] = a;
                    }
            } else {
                const float* ma = s_ma + (c*8 + t)*16;
                const float* bb = s_bb + (c*8 + t)*4;
#pragma unroll
                for (int i = 0; i < 4; ++i)
#pragma unroll
                    for (int kp = 0; kp < 2; ++kp) {
                        ull a = *(const ull*)(bb + 2*kp);
                        a = ffma2(cb2[4*i+0], *(const ull*)(ma + 0  + 2*kp), a);
                        a = ffma2(cb2[4*i+1], *(const ull*)(ma + 4  + 2*kp), a);
                        a = ffma2(cb2[4*i+2], *(const ull*)(ma + 8  + 2*kp), a);
                        a = ffma2(cb2[4*i+3], *(const ull*)(ma + 12 + 2*kp), a);
                        u2[c][2*i + kp] = a;
                    }
            }
        }

        float b0 = 0.f, b1 = 0.f, b2 = 0.f, b3 = 0.f;
        ull p2[8];

#pragma unroll
        for (int it = 0; it < 3; ++it) {
            ull rb0 = pk(sigf(b0), sigf(b0));
            ull rb1 = pk(sigf(b1), sigf(b1));
            ull rb2 = pk(sigf(b2), sigf(b2));
            ull rb3 = pk(sigf(b3), sigf(b3));
#pragma unroll
            for (int m = 0; m < 8; ++m) {
                ull a = fmul2(u2[0][m], rb0);
                a = ffma2(u2[1][m], rb1, a);
                a = ffma2(u2[2][m], rb2, a);
                p2[m] = ffma2(u2[3][m], rb3, a);
            }
            if (s == 0) {                         // psquash
                float mx = 0.f;
#pragma unroll
                for (int m = 0; m < 8; ++m) {
                    float2 f = upk(p2[m]);
                    mx = fmaxf(mx, fabsf(f.x));
                    mx = fmaxf(mx, fabsf(f.y));
                }
                float inv = 1.0f / mx;
                ull ib = pk(inv, inv);
#pragma unroll
                for (int m = 0; m < 8; ++m) p2[m] = fmul2(p2[m], ib);
            } else {                              // matwo squash
                ull sp = fmul2(p2[0], p2[0]);
#pragma unroll
                for (int m = 1; m < 8; ++m) sp = ffma2(p2[m], p2[m], sp);
                float2 f = upk(sp);
                float sq = f.x + f.y;
                float sc = sq / (1.0f + sq) * rsqrtf(sq + 1e-9f);
                ull sb = pk(sc, sc);
#pragma unroll
                for (int m = 0; m < 8; ++m) p2[m] = fmul2(p2[m], sb);
            }
            if (it == 2) break;                   // last pass: p2 holds v

            float q0, q1, q2, q3;
            {
                ull a0 = fmul2(u2[0][0], p2[0]);
                ull a1 = fmul2(u2[1][0], p2[0]);
                ull a2 = fmul2(u2[2][0], p2[0]);
                ull a3 = fmul2(u2[3][0], p2[0]);
#pragma unroll
                for (int m = 1; m < 8; ++m) {
                    a0 = ffma2(u2[0][m], p2[m], a0);
                    a1 = ffma2(u2[1][m], p2[m], a1);
                    a2 = ffma2(u2[2][m], p2[m], a2);
                    a3 = ffma2(u2[3][m], p2[m], a3);
                }
                float2 f0 = upk(a0), f1 = upk(a1), f2 = upk(a2), f3 = upk(a3);
                q0 = f0.x + f0.y; q1 = f1.x + f1.y;
                q2 = f2.x + f2.y; q3 = f3.x + f3.y;
            }
            // double-buffered float4 exchange: 1 barrier per iteration
            float4* exw = (float4*)(s_ex + it*1024) + tid;
            const float4* exr = (float4*)(s_ex + it*1024) + (tid ^ 128);
            *exw = make_float4(q0, q1, q2, q3);
            __syncthreads();
            float4 o = *exr;
            b0 += q0 * o.x;
            b1 += q1 * o.y;
            b2 += q2 * o.z;
            b3 += q3 * o.w;
        }

        // out[n][t][z][h][w]
        float* ob = out + ((long)(n*8 + t)*32 + s*16)*16384 + h*128 + w0 + pix;
#pragma unroll
        for (int m = 0; m < 8; ++m) {
            float2 f = upk(p2[m]);
            ob[(long)(2*m  )*16384] = f.x;
            ob[(long)(2*m+1)*16384] = f.y;
        }
    }
}

extern "C" void kernel_launch(void* const* d_in, const int* in_sizes, int n_in,
                              void* d_out, int out_size)
{
    const float* x  = (const float*)d_in[0];
    const float* Wc = (const float*)d_in[1];
    const float* Wp = (const float*)d_in[2];
    const float* Wa = (const float*)d_in[3];
    const float* ba = (const float*)d_in[4];
    float* out = (float*)d_out;

    cudaFuncSetAttribute(caps_kernel,
                         cudaFuncAttributeMaxDynamicSharedMemorySize,
                         SMEM_BYTES);

    dim3 grid(8, 128, 2);   // (w/16, h, n)
    caps_kernel<<<grid, 256, SMEM_BYTES>>>(x, Wc, Wp, Wa, ba, out);
}

// round 17
// speedup vs baseline: 1.5783x; 1.5783x over previous
#include <cuda_runtime.h>

// ---------------------------------------------------------------------------
// Caps2dMatwo fused kernel, v11 = v7b (49.6us) with ONE change:
// phase-B thread bits chh<->zh swapped so duplicate conv-tap loads land in
// the SAME warp (lanes l and l+16) -> smem broadcast dedup halves tap
// wavefronts (144 -> 72 wf/warp).  Everything else identical to v7b.
// Shapes: N=2, T0=4 (c), T1=8, H=W=128, PD=AD=4, Z=32, KS=3, ROUTINGS=3.
// ---------------------------------------------------------------------------

typedef unsigned long long ull;

#define SX_SIZE   (4*3*18*34)          // 7344 floats: [(c*3+kh)*18+col]*34+z
#define CV_PSTR   36
#define CV_SIZE   (32*16*CV_PSTR)      // 18432 floats: [(c*8+ch)*16+pix]*36+z
#define SMEM_FLOATS (SX_SIZE + CV_SIZE + 288 + 512 + 512 + 128)
#define SMEM_BYTES (SMEM_FLOATS * 4)   // 108,864 bytes -> 2 blocks/SM

__device__ __forceinline__ float sigf(float v) {
    return 1.0f / (1.0f + __expf(-v));
}
__device__ __forceinline__ ull pk(float a, float b) {
    ull r; asm("mov.b64 %0, {%1, %2};" : "=l"(r) : "f"(a), "f"(b)); return r;
}
__device__ __forceinline__ float2 upk(ull v) {
    float2 r; asm("mov.b64 {%0, %1}, %2;" : "=f"(r.x), "=f"(r.y) : "l"(v)); return r;
}
__device__ __forceinline__ ull ffma2(ull a, ull b, ull c) {
    ull d; asm("fma.rn.f32x2 %0, %1, %2, %3;" : "=l"(d) : "l"(a), "l"(b), "l"(c)); return d;
}
__device__ __forceinline__ ull fmul2(ull a, ull b) {
    ull d; asm("mul.rn.f32x2 %0, %1, %2;" : "=l"(d) : "l"(a), "l"(b)); return d;
}

__global__ void __launch_bounds__(256, 2)
caps_kernel(const float* __restrict__ x,     // (2,4,32,128,128)
            const float* __restrict__ Wc,    // (4,3,3,1,8)  flat 288
            const float* __restrict__ Wp,    // (4,16,8)     flat 512
            const float* __restrict__ Wa,    // (4,16,8)     flat 512
            const float* __restrict__ ba,    // (4,8)        flat 32
            float* __restrict__ out)         // (2,8,32,128,128)
{
    extern __shared__ float sm[];
    float* s_x  = sm;                    // 7344, z-innermost; reused as s_ex
    float* s_cv = s_x + SX_SIZE;         // 18432
    float* s_wc = s_cv + CV_SIZE;        // 288  [c][kh*3+kw][t1]
    float* s_mp = s_wc + 288;            // 512  [c][t][j][k] normalized
    float* s_ma = s_mp + 512;            // 512  [c][t][j][k]
    float* s_bb = s_ma + 512;            // 128  [c][t][k] = b_app*sum_j mapp
    float* s_ex = s_x;                   // aliased: phase C only

    const int tid = threadIdx.x;
    const int w0  = blockIdx.x * 16;
    const int h   = blockIdx.y;
    const int n   = blockIdx.z;

    // ---- weights into smem (256-thread safe) ----
    if (tid < 144) {                             // 288 conv weights, 2 each
        s_wc[tid]       = Wc[tid];
        s_wc[tid + 144] = Wc[tid + 144];
    }
    s_ma[tid]       = Wa[tid];
    s_ma[tid + 256] = Wa[tid + 256];
    if (tid < 128) {
        int q = tid;                             // one (c,t,k) each
        int c = q >> 5, t = (q >> 2) & 7, k = q & 3;
        const float* wpp = Wp + c*128 + t*16 + k;
        float m0 = wpp[0], m1 = wpp[4], m2 = wpp[8], m3 = wpp[12];
        float inv = rsqrtf(fmaxf(m0*m0 + m1*m1 + m2*m2 + m3*m3, 1e-12f));
        float* d = s_mp + (c*8 + t)*16 + k;
        d[0] = m0*inv; d[4] = m1*inv; d[8] = m2*inv; d[12] = m3*inv;
        const float* wap = Wa + c*128 + t*16 + k;
        s_bb[(c*8 + t)*4 + k] = ba[c*8 + t] * (wap[0] + wap[4] + wap[8] + wap[12]);
    }

    // ---- x tile loader (transposed: z innermost).  col 1..16 = w0..w0+15,
    //      col 0 = w0-1, col 17 = w0+16;  rows kh = h-1..h+1.  ----
#pragma unroll
    for (int r3 = 0; r3 < 3; ++r3) {
        const int gr = h + r3 - 1;
        const bool ok = (gr >= 0) && (gr < 128);
#pragma unroll
        for (int it = 0; it < 2; ++it) {
            int unit = tid + it*256;              // cz*4 + colgrp
            int cz   = unit >> 2;
            int col4 = (unit & 3) * 4;
            float4 v = make_float4(0.f, 0.f, 0.f, 0.f);
            if (ok)
                v = *(const float4*)(x + (((long)n*128 + cz)*128 + gr)*128 + w0 + col4);
            int c = cz >> 5, z = cz & 31;
            float* base = s_x + ((c*3 + r3)*18 + 1 + col4)*34 + z;
            base[0]    = v.x;
            base[34]   = v.y;
            base[68]   = v.z;
            base[102]  = v.w;
        }
    }
    {                                             // halo columns
        int cz   = tid & 127;
        int side = tid >> 7;                      // 0 = left, 1 = right
        int c = cz >> 5, z = cz & 31;
        const bool okc = side ? (w0 + 16 < 128) : (w0 > 0);
        const int  gc  = side ? (w0 + 16) : (w0 - 1);
        const int  sc  = side ? 17 : 0;
#pragma unroll
        for (int r3 = 0; r3 < 3; ++r3) {
            int gr = h + r3 - 1;
            float v = 0.f;
            if (okc && gr >= 0 && gr < 128)
                v = x[(((long)n*128 + cz)*128 + gr)*128 + gc];
            s_x[((c*3 + r3)*18 + sc)*34 + z] = v;
        }
    }
    __syncthreads();

    // ---- Phase B: conv, f32x2 over z-pairs.  thread=(c,zh,chh,pix)
    //      chh on bit4, zh on bit5: lanes l and l+16 share tap addresses
    //      -> smem broadcast dedup (1 wavefront per tap LDS.64). ----
    {
        const int c   = tid >> 6;                 // warp-uniform
        const int zh  = (tid >> 5) & 1;           // warp-uniform (was bit4)
        const int chh = (tid >> 4) & 1;           // half-warp     (was bit5)
        const int pix = tid & 15;

        ull w2[9][4];                             // (w,w) broadcast pairs
#pragma unroll
        for (int p = 0; p < 9; ++p)
#pragma unroll
            for (int l = 0; l < 4; ++l) {
                float wv = s_wc[(c*9 + p)*8 + chh*4 + l];
                w2[p][l] = pk(wv, wv);
            }

        const float* xc = s_x + (c*3*18 + pix)*34;  // + kh*612 + kw*34 + z

#pragma unroll
        for (int ck = 0; ck < 4; ++ck) {
            const int z0 = zh*16 + ck*4;
            ull acc[4][2];
#pragma unroll
            for (int l = 0; l < 4; ++l) { acc[l][0] = 0ULL; acc[l][1] = 0ULL; }
#pragma unroll
            for (int zp = 0; zp < 2; ++zp) {
                const float* xb = xc + z0 + 2*zp;
#pragma unroll
                for (int kh = 0; kh < 3; ++kh)
#pragma unroll
                    for (int kw = 0; kw < 3; ++kw) {
                        ull xv = *(const ull*)(xb + kh*612 + kw*34);
#pragma unroll
                        for (int l = 0; l < 4; ++l)
                            acc[l][zp] = ffma2(xv, w2[kh*3+kw][l], acc[l][zp]);
                    }
            }
#pragma unroll
            for (int l = 0; l < 4; ++l)
                *(ulonglong2*)(s_cv + ((c*8 + chh*4 + l)*16 + pix)*CV_PSTR + z0) =
                    make_ulonglong2(acc[l][0], acc[l][1]);
        }
    }
    __syncthreads();

    // ---- Phase C (v7b, verbatim): u_hat f32x2 + routing, barrier exchange.
    //      thread = s*128 + t*16 + pix ----
    {
        const int s   = tid >> 7;                 // warp-uniform
        const int t   = (tid >> 4) & 7;           // half-warp
        const int pix = tid & 15;
        const int t1  = (t >> 1) + (s ? 4 : 0);   // conv channel
        const int zb  = (t & 1) << 4;

        ull u2[4][8];                             // u_hat, z-pairs

        const ull coordp = pk((float)(w0 + pix) * (1.0f/128.0f),
                              (float)h * (1.0f/128.0f));

#pragma unroll
        for (int c = 0; c < 4; ++c) {
            const float* cb = s_cv + ((c*8 + t1)*16 + pix)*CV_PSTR + zb;
            ulonglong2 A  = *(const ulonglong2*)(cb + 0);
            ulonglong2 B  = *(const ulonglong2*)(cb + 4);
            ulonglong2 C2 = *(const ulonglong2*)(cb + 8);
            ulonglong2 D  = *(const ulonglong2*)(cb + 12);
            ull cpr[8] = {A.x, A.y, B.x, B.y, C2.x, C2.y, D.x, D.y};
            ull cb2[16];
#pragma unroll
            for (int m = 0; m < 8; ++m) {
                float2 f = upk(cpr[m]);
                cb2[2*m]   = pk(f.x, f.x);
                cb2[2*m+1] = pk(f.y, f.y);
            }
            if (s == 0) {
                const float* mp = s_mp + (c*8 + t)*16;
#pragma unroll
                for (int i = 0; i < 4; ++i)
#pragma unroll
                    for (int kp = 0; kp < 2; ++kp) {
                        ull a = fmul2(cb2[4*i+0], *(const ull*)(mp + 0  + 2*kp));
                        a = ffma2(cb2[4*i+1], *(const ull*)(mp + 4  + 2*kp), a);
                        a = ffma2(cb2[4*i+2], *(const ull*)(mp + 8  + 2*kp), a);
                        a = ffma2(cb2[4*i+3], *(const ull*)(mp + 12 + 2*kp), a);
                        if (kp == 0) a = ffma2(cb2[4*i+3], coordp, a);
                        u2[c][2*i + kp] = a;
                    }
            } else {
                const float* ma = s_ma + (c*8 + t)*16;
                const float* bb = s_bb + (c*8 + t)*4;
#pragma unroll
                for (int i = 0; i < 4; ++i)
#pragma unroll
                    for (int kp = 0; kp < 2; ++kp) {
                        ull a = *(const ull*)(bb + 2*kp);
                        a = ffma2(cb2[4*i+0], *(const ull*)(ma + 0  + 2*kp), a);
                        a = ffma2(cb2[4*i+1], *(const ull*)(ma + 4  + 2*kp), a);
                        a = ffma2(cb2[4*i+2], *(const ull*)(ma + 8  + 2*kp), a);
                        a = ffma2(cb2[4*i+3], *(const ull*)(ma + 12 + 2*kp), a);
                        u2[c][2*i + kp] = a;
                    }
            }
        }

        float b0 = 0.f, b1 = 0.f, b2 = 0.f, b3 = 0.f;
        ull p2[8];

#pragma unroll
        for (int it = 0; it < 3; ++it) {
            ull rb0 = pk(sigf(b0), sigf(b0));
            ull rb1 = pk(sigf(b1), sigf(b1));
            ull rb2 = pk(sigf(b2), sigf(b2));
            ull rb3 = pk(sigf(b3), sigf(b3));
#pragma unroll
            for (int m = 0; m < 8; ++m) {
                ull a = fmul2(u2[0][m], rb0);
                a = ffma2(u2[1][m], rb1, a);
                a = ffma2(u2[2][m], rb2, a);
                p2[m] = ffma2(u2[3][m], rb3, a);
            }
            if (s == 0) {                         // psquash
                float mx = 0.f;
#pragma unroll
                for (int m = 0; m < 8; ++m) {
                    float2 f = upk(p2[m]);
                    mx = fmaxf(mx, fabsf(f.x));
                    mx = fmaxf(mx, fabsf(f.y));
                }
                float inv = 1.0f / mx;
                ull ib = pk(inv, inv);
#pragma unroll
                for (int m = 0; m < 8; ++m) p2[m] = fmul2(p2[m], ib);
            } else {                              // matwo squash
                ull sp = fmul2(p2[0], p2[0]);
#pragma unroll
                for (int m = 1; m < 8; ++m) sp = ffma2(p2[m], p2[m], sp);
                float2 f = upk(sp);
                float sq = f.x + f.y;
                float sc = sq / (1.0f + sq) * rsqrtf(sq + 1e-9f);
                ull sb = pk(sc, sc);
#pragma unroll
                for (int m = 0; m < 8; ++m) p2[m] = fmul2(p2[m], sb);
            }
            if (it == 2) break;                   // last pass: p2 holds v

            float q0, q1, q2, q3;
            {
                ull a0 = fmul2(u2[0][0], p2[0]);
                ull a1 = fmul2(u2[1][0], p2[0]);
                ull a2 = fmul2(u2[2][0], p2[0]);
                ull a3 = fmul2(u2[3][0], p2[0]);
#pragma unroll
                for (int m = 1; m < 8; ++m) {
                    a0 = ffma2(u2[0][m], p2[m], a0);
                    a1 = ffma2(u2[1][m], p2[m], a1);
                    a2 = ffma2(u2[2][m], p2[m], a2);
                    a3 = ffma2(u2[3][m], p2[m], a3);
                }
                float2 f0 = upk(a0), f1 = upk(a1), f2 = upk(a2), f3 = upk(a3);
                q0 = f0.x + f0.y; q1 = f1.x + f1.y;
                q2 = f2.x + f2.y; q3 = f3.x + f3.y;
            }
            // double-buffered float4 exchange: 1 barrier per iteration
            float4* exw = (float4*)(s_ex + it*1024) + tid;
            const float4* exr = (float4*)(s_ex + it*1024) + (tid ^ 128);
            *exw = make_float4(q0, q1, q2, q3);
            __syncthreads();
            float4 o = *exr;
            b0 += q0 * o.x;
            b1 += q1 * o.y;
            b2 += q2 * o.z;
            b3 += q3 * o.w;
        }

        // out[n][t][z][h][w]
        float* ob = out + ((long)(n*8 + t)*32 + s*16)*16384 + h*128 + w0 + pix;
#pragma unroll
        for (int m = 0; m < 8; ++m) {
            float2 f = upk(p2[m]);
            ob[(long)(2*m  )*16384] = f.x;
            ob[(long)(2*m+1)*16384] = f.y;
        }
    }
}

extern "C" void kernel_launch(void* const* d_in, const int* in_sizes, int n_in,
                              void* d_out, int out_size)
{
    const float* x  = (const float*)d_in[0];
    const float* Wc = (const float*)d_in[1];
    const float* Wp = (const float*)d_in[2];
    const float* Wa = (const float*)d_in[3];
    const float* ba = (const float*)d_in[4];
    float* out = (float*)d_out;

    cudaFuncSetAttribute(caps_kernel,
                         cudaFuncAttributeMaxDynamicSharedMemorySize,
                         SMEM_BYTES);

    dim3 grid(8, 128, 2);   // (w/16, h, n)
    caps_kernel<<<grid, 256, SMEM_BYTES>>>(x, Wc, Wp, Wa, ba, out);
}